// round 8
// baseline (speedup 1.0000x reference)
#include <cuda_runtime.h>
#include <cstdint>
#include <cstddef>

// Problem constants
#define BATCH   1024
#define SEQ     512
#define NFEAT   64
#define HID     128
#define GATES   512          // 4*HID
#define NOUT    128

// LSTM persistent kernel config
#define NCTA    128
#define BR      8            // batch rows per CTA (1024/128)
#define LTHREADS 512
#define SMEM_K4 20           // k4 blocks of W_hh in smem (20*512*16B = 160 KB)
#define STR_K4  12           // k4 blocks streamed from L2 each step (regs, prefetched)

// Scratch (device globals; no allocations allowed)
__device__ float  g_xg[(size_t)BATCH * SEQ * GATES];   // x@W_ih^T + b_ih + b_hh, [bt][gate]
__device__ float4 g_Wq[32 * GATES];                    // W_hh repacked: [k4][row] = W_hh[row][4k4..4k4+3]

// ---------------------------------------------------------------------------
// f32x2 packed FMA helper
// ---------------------------------------------------------------------------
__device__ __forceinline__ void ffma2(unsigned long long& d,
                                      unsigned long long a,
                                      unsigned long long b) {
    asm("fma.rn.f32x2 %0, %1, %2, %0;" : "+l"(d) : "l"(a), "l"(b));
}

__device__ __forceinline__ float hsum2(unsigned long long v) {
    float lo = __int_as_float((unsigned int)(v & 0xffffffffULL));
    float hi = __int_as_float((unsigned int)(v >> 32));
    return lo + hi;
}

__device__ __forceinline__ float sigmoid_f(float x) {
    return __fdividef(1.0f, 1.0f + __expf(-x));
}
__device__ __forceinline__ float tanh_f(float x) {
    return 1.0f - __fdividef(2.0f, __expf(2.0f * x) + 1.0f);
}

// ---------------------------------------------------------------------------
// Kernel 1: xg[bt][n] = sum_f x[bt][f] * W_ih[n][f] + b_ih[n] + b_hh[n]
// Block (0,0) additionally repacks W_hh into g_Wq (consumed only by the NEXT
// kernel, so intra-grid ordering is irrelevant).
// ---------------------------------------------------------------------------
__global__ __launch_bounds__(256) void xg_kernel(const float* __restrict__ x,
                                                 const float* __restrict__ Wih,
                                                 const float* __restrict__ Whh,
                                                 const float* __restrict__ b_ih,
                                                 const float* __restrict__ b_hh) {
    __shared__ float As[64][66];
    __shared__ float Bs[64][66];

    const int bt0 = blockIdx.x * 64;
    const int n0  = blockIdx.y * 64;
    const int tid = threadIdx.x;

    // Side duty: repack W_hh [512][128] -> g_Wq[k4][row] (float4 along k)
    if (blockIdx.x == 0 && blockIdx.y == 0) {
#pragma unroll
        for (int p = 0; p < 2; p++) {
            int row = tid + p * 256;              // 0..511
            const float4* src = (const float4*)(Whh + (size_t)row * HID);
#pragma unroll
            for (int k4 = 0; k4 < 32; k4++)
                g_Wq[k4 * GATES + row] = src[k4];
        }
    }

    const float4* Ag = (const float4*)(x   + (size_t)bt0 * NFEAT);
    const float4* Bg = (const float4*)(Wih + (size_t)n0  * NFEAT);
#pragma unroll
    for (int p = 0; p < 4; p++) {
        int v = tid + p * 256;
        int m = v >> 4;
        int k = (v & 15) * 4;
        float4 qa = Ag[v];
        As[m][k] = qa.x; As[m][k+1] = qa.y; As[m][k+2] = qa.z; As[m][k+3] = qa.w;
        float4 qb = Bg[v];
        Bs[m][k] = qb.x; Bs[m][k+1] = qb.y; Bs[m][k+2] = qb.z; Bs[m][k+3] = qb.w;
    }
    __syncthreads();

    const int tx = tid & 31;
    const int ty = tid >> 5;

    unsigned long long acc[8][2];
#pragma unroll
    for (int i = 0; i < 8; i++)
#pragma unroll
        for (int j = 0; j < 2; j++) acc[i][j] = 0ULL;

#pragma unroll
    for (int k2 = 0; k2 < 32; k2++) {
        unsigned long long a2[8], b2[2];
#pragma unroll
        for (int i = 0; i < 8; i++)
            a2[i] = *(const unsigned long long*)&As[ty + i * 8][k2 * 2];
#pragma unroll
        for (int j = 0; j < 2; j++)
            b2[j] = *(const unsigned long long*)&Bs[tx + j * 32][k2 * 2];
#pragma unroll
        for (int i = 0; i < 8; i++)
#pragma unroll
            for (int j = 0; j < 2; j++)
                ffma2(acc[i][j], a2[i], b2[j]);
    }

    float bias[2];
#pragma unroll
    for (int j = 0; j < 2; j++) {
        int n = n0 + tx + j * 32;
        bias[j] = __ldg(&b_ih[n]) + __ldg(&b_hh[n]);
    }

#pragma unroll
    for (int i = 0; i < 8; i++) {
        int m = bt0 + ty + i * 8;
#pragma unroll
        for (int j = 0; j < 2; j++) {
            int n = n0 + tx + j * 32;
            g_xg[(size_t)m * GATES + n] = hsum2(acc[i][j]) + bias[j];
        }
    }
}

// ---------------------------------------------------------------------------
// Kernel 2: persistent LSTM, gate-column ownership (crossbar-efficient).
// FMA phase: thread n in [0,512) computes gate pre-activation n for all 8
//   batch rows (weights read once per thread; h broadcast from smem).
//   Weights: k4 0..19 smem-cached; k4 20..31 streamed from L2 (g_Wq, fully
//   register-prefetched at step top; L2-resident, coalesced LDG.128).
// Elementwise phase: thread (rp,j) handles rows rp, rp+4: reads gs + its
//   register-prefetched xg, MUFU sigmoid/tanh, c in regs, h in smem.
// ---------------------------------------------------------------------------
extern __shared__ char smem_raw[];

__global__ __launch_bounds__(LTHREADS, 1) void lstm_kernel(
        const float* __restrict__ W_out,
        const float* __restrict__ b_out,
        float* __restrict__ out) {

    // smem carve: weights (163840B) | h (4096B) | gates (16384B)
    ulonglong2* w4s = (ulonglong2*)smem_raw;                        // [SMEM_K4][512]
    float* h_s = (float*)(smem_raw + SMEM_K4 * GATES * 16);         // [8][128]
    float* gs  = (float*)(smem_raw + SMEM_K4 * GATES * 16 + 4096);  // [8][512]

    const int tid = threadIdx.x;
    const int b0  = blockIdx.x * BR;
    const int n   = tid;
    const int j   = tid & 127;
    const int rp  = tid >> 7;          // 0..3; elementwise rows rp, rp+4

    const ulonglong2* Wg = (const ulonglong2*)g_Wq;

    // Prologue: smem weights (k4 0..19), zero h
#pragma unroll
    for (int p = 0; p < SMEM_K4; p++) {
        int idx = tid + p * LTHREADS;
        w4s[idx] = Wg[idx];
    }
    h_s[tid & (BR * HID - 1)] = 0.0f;   // 512 threads cover 1024 floats twice
    h_s[(tid + LTHREADS) & (BR * HID - 1)] = 0.0f;
    __syncthreads();

    float cst[2] = {0.0f, 0.0f};

    for (int t = 0; t < SEQ; t++) {
        // -- Prefetch: streamed weights (independent of h) + this step's xg --
        ulonglong2 wbuf[STR_K4];
#pragma unroll
        for (int s = 0; s < STR_K4; s++)
            wbuf[s] = Wg[(SMEM_K4 + s) * GATES + n];

        float xg_v[2][4];
#pragma unroll
        for (int p = 0; p < 2; p++) {
            size_t base = ((size_t)((b0 + rp + p * 4) * SEQ + t)) * GATES + j;
#pragma unroll
            for (int g = 0; g < 4; g++)
                xg_v[p][g] = __ldg(&g_xg[base + g * HID]);
        }

        // -- FMA phase: gs[r][n] = sum_k h[r][k] * Whh[n][k] --
        unsigned long long acc[BR];
#pragma unroll
        for (int r = 0; r < BR; r++) acc[r] = 0ULL;

#pragma unroll
        for (int k4 = 0; k4 < SMEM_K4; k4++) {
            ulonglong2 w = w4s[k4 * GATES + n];
#pragma unroll
            for (int r = 0; r < BR; r++) {
                ulonglong2 hh = *(const ulonglong2*)&h_s[r * HID + k4 * 4];
                ffma2(acc[r], hh.x, w.x);
                ffma2(acc[r], hh.y, w.y);
            }
        }
#pragma unroll
        for (int s = 0; s < STR_K4; s++) {
            int k4 = SMEM_K4 + s;
#pragma unroll
            for (int r = 0; r < BR; r++) {
                ulonglong2 hh = *(const ulonglong2*)&h_s[r * HID + k4 * 4];
                ffma2(acc[r], hh.x, wbuf[s].x);
                ffma2(acc[r], hh.y, wbuf[s].y);
            }
        }

#pragma unroll
        for (int r = 0; r < BR; r++)
            gs[r * GATES + n] = hsum2(acc[r]);

        __syncthreads();

        // -- Elementwise phase: nonlinearity + state update --
#pragma unroll
        for (int p = 0; p < 2; p++) {
            int r = rp + p * 4;
            float gi = gs[r * GATES + j]             + xg_v[p][0];
            float gf = gs[r * GATES + 128 + j]       + xg_v[p][1];
            float gg = gs[r * GATES + 256 + j]       + xg_v[p][2];
            float go = gs[r * GATES + 384 + j]       + xg_v[p][3];
            float iv = sigmoid_f(gi);
            float fv = sigmoid_f(gf);
            float gv = tanh_f(gg);
            float ov = sigmoid_f(go);
            float cc = fv * cst[p] + iv * gv;
            cst[p] = cc;
            h_s[r * HID + j] = ov * tanh_f(cc);
        }
        __syncthreads();
    }

    // -- Output projection: out[b][o] = h[b] . W_out[o] + b_out[o] --
#pragma unroll
    for (int p = 0; p < 2; p++) {
        int idx = tid + p * LTHREADS;      // 0..1023 -> (r, o)
        int r = idx >> 7;
        int o = idx & 127;
        const float4* wo = (const float4*)(W_out + (size_t)o * HID);
        const float4* hrr = (const float4*)&h_s[r * HID];
        float s = __ldg(&b_out[o]);
#pragma unroll
        for (int k4 = 0; k4 < 32; k4++) {
            float4 w = wo[k4];
            float4 h = hrr[k4];
            s += w.x * h.x + w.y * h.y + w.z * h.z + w.w * h.w;
        }
        out[(size_t)(b0 + r) * NOUT + o] = s;
    }
}

// ---------------------------------------------------------------------------
// Launch (2 kernels)
// ---------------------------------------------------------------------------
extern "C" void kernel_launch(void* const* d_in, const int* in_sizes, int n_in,
                              void* d_out, int out_size) {
    const float* x     = (const float*)d_in[0];
    const float* W_ih  = (const float*)d_in[1];
    const float* W_hh  = (const float*)d_in[2];
    const float* b_ih  = (const float*)d_in[3];
    const float* b_hh  = (const float*)d_in[4];
    const float* W_out = (const float*)d_in[5];
    const float* b_out = (const float*)d_in[6];
    float* out = (float*)d_out;

    const int lstm_smem = SMEM_K4 * GATES * 16 + 4096 + BR * GATES * 4; // 160K+4K+16K
    cudaFuncSetAttribute(lstm_kernel,
                         cudaFuncAttributeMaxDynamicSharedMemorySize, lstm_smem);

    dim3 grid1((BATCH * SEQ) / 64, GATES / 64);
    xg_kernel<<<grid1, 256>>>(x, W_ih, W_hh, b_ih, b_hh);

    lstm_kernel<<<NCTA, LTHREADS, lstm_smem>>>(W_out, b_out, out);
}

// round 12
// speedup vs baseline: 1.7826x; 1.7826x over previous
#include <cuda_runtime.h>
#include <cstdint>
#include <cstddef>

// Problem constants
#define BATCH   1024
#define SEQ     512
#define NFEAT   64
#define HID     128
#define GATES   512          // 4*HID
#define NOUT    128

// LSTM persistent kernel config
#define NCTA    128
#define BR      8            // batch rows per CTA (1024/128)
#define LTHREADS 512
#define SMEM_K4 24           // k4 blocks of W_hh in smem (24*512*16B = 192 KB)
#define REG_K4  8            // k4 blocks held in registers per thread (8*16B = 32 regs)

// Scratch (device globals; no allocations allowed)
__device__ float  g_xg[(size_t)BATCH * SEQ * GATES];   // x@W_ih^T + b_ih + b_hh, [bt][gate]
__device__ float4 g_Wq[32 * GATES];                    // W_hh repacked: [k4][row] = W_hh[row][4k4..4k4+3]

// ---------------------------------------------------------------------------
// f32x2 packed FMA helper
// ---------------------------------------------------------------------------
__device__ __forceinline__ void ffma2(unsigned long long& d,
                                      unsigned long long a,
                                      unsigned long long b) {
    asm("fma.rn.f32x2 %0, %1, %2, %0;" : "+l"(d) : "l"(a), "l"(b));
}

__device__ __forceinline__ float hsum2(unsigned long long v) {
    float lo = __int_as_float((unsigned int)(v & 0xffffffffULL));
    float hi = __int_as_float((unsigned int)(v >> 32));
    return lo + hi;
}

__device__ __forceinline__ float sigmoid_f(float x) {
    return __fdividef(1.0f, 1.0f + __expf(-x));
}
__device__ __forceinline__ float tanh_f(float x) {
    return 1.0f - __fdividef(2.0f, __expf(2.0f * x) + 1.0f);
}

// ---------------------------------------------------------------------------
// Kernel 1: xg[bt][n] = sum_f x[bt][f] * W_ih[n][f] + b_ih[n] + b_hh[n]
// Block (0,0) additionally repacks W_hh into g_Wq (consumed only by the NEXT
// kernel, so intra-grid ordering is irrelevant).
// ---------------------------------------------------------------------------
__global__ __launch_bounds__(256) void xg_kernel(const float* __restrict__ x,
                                                 const float* __restrict__ Wih,
                                                 const float* __restrict__ Whh,
                                                 const float* __restrict__ b_ih,
                                                 const float* __restrict__ b_hh) {
    __shared__ float As[64][66];
    __shared__ float Bs[64][66];

    const int bt0 = blockIdx.x * 64;
    const int n0  = blockIdx.y * 64;
    const int tid = threadIdx.x;

    // Side duty: repack W_hh [512][128] -> g_Wq[k4][row] (float4 along k)
    if (blockIdx.x == 0 && blockIdx.y == 0) {
#pragma unroll
        for (int p = 0; p < 2; p++) {
            int row = tid + p * 256;              // 0..511
            const float4* src = (const float4*)(Whh + (size_t)row * HID);
#pragma unroll
            for (int k4 = 0; k4 < 32; k4++)
                g_Wq[k4 * GATES + row] = src[k4];
        }
    }

    const float4* Ag = (const float4*)(x   + (size_t)bt0 * NFEAT);
    const float4* Bg = (const float4*)(Wih + (size_t)n0  * NFEAT);
#pragma unroll
    for (int p = 0; p < 4; p++) {
        int v = tid + p * 256;
        int m = v >> 4;
        int k = (v & 15) * 4;
        float4 qa = Ag[v];
        As[m][k] = qa.x; As[m][k+1] = qa.y; As[m][k+2] = qa.z; As[m][k+3] = qa.w;
        float4 qb = Bg[v];
        Bs[m][k] = qb.x; Bs[m][k+1] = qb.y; Bs[m][k+2] = qb.z; Bs[m][k+3] = qb.w;
    }
    __syncthreads();

    const int tx = tid & 31;
    const int ty = tid >> 5;

    unsigned long long acc[8][2];
#pragma unroll
    for (int i = 0; i < 8; i++)
#pragma unroll
        for (int j = 0; j < 2; j++) acc[i][j] = 0ULL;

#pragma unroll
    for (int k2 = 0; k2 < 32; k2++) {
        unsigned long long a2[8], b2[2];
#pragma unroll
        for (int i = 0; i < 8; i++)
            a2[i] = *(const unsigned long long*)&As[ty + i * 8][k2 * 2];
#pragma unroll
        for (int j = 0; j < 2; j++)
            b2[j] = *(const unsigned long long*)&Bs[tx + j * 32][k2 * 2];
#pragma unroll
        for (int i = 0; i < 8; i++)
#pragma unroll
            for (int j = 0; j < 2; j++)
                ffma2(acc[i][j], a2[i], b2[j]);
    }

    float bias[2];
#pragma unroll
    for (int j = 0; j < 2; j++) {
        int n = n0 + tx + j * 32;
        bias[j] = __ldg(&b_ih[n]) + __ldg(&b_hh[n]);
    }

#pragma unroll
    for (int i = 0; i < 8; i++) {
        int m = bt0 + ty + i * 8;
#pragma unroll
        for (int j = 0; j < 2; j++) {
            int n = n0 + tx + j * 32;
            g_xg[(size_t)m * GATES + n] = hsum2(acc[i][j]) + bias[j];
        }
    }
}

// ---------------------------------------------------------------------------
// Kernel 2: persistent LSTM, gate-column ownership.
// Weights: k4 0..23 in smem (192 KB); k4 24..31 held PERSISTENTLY in each
// thread's registers for its own gate column n (32 regs). ZERO weight traffic
// from L2/DRAM inside the step loop, no spill risk (in-loop demand ~90 regs).
// FMA phase: thread n computes gate pre-activation n for all 8 batch rows
//   (weight read once per thread; h broadcast LDS).
// Elementwise phase: thread (rp,j) handles rows rp, rp+4 with MUFU math.
// ---------------------------------------------------------------------------
extern __shared__ char smem_raw[];

__global__ __launch_bounds__(LTHREADS, 1) void lstm_kernel(
        const float* __restrict__ W_out,
        const float* __restrict__ b_out,
        float* __restrict__ out) {

    // smem carve: weights (196608B) | h (4096B) | gates (16384B)
    ulonglong2* w4s = (ulonglong2*)smem_raw;                        // [SMEM_K4][512]
    float* h_s = (float*)(smem_raw + SMEM_K4 * GATES * 16);         // [8][128]
    float* gs  = (float*)(smem_raw + SMEM_K4 * GATES * 16 + 4096);  // [8][512]

    const int tid = threadIdx.x;
    const int b0  = blockIdx.x * BR;
    const int n   = tid;
    const int j   = tid & 127;
    const int rp  = tid >> 7;          // 0..3; elementwise rows rp, rp+4

    const ulonglong2* Wg = (const ulonglong2*)g_Wq;

    // Prologue: smem weights (k4 0..23), persistent register weights (24..31)
#pragma unroll
    for (int p = 0; p < SMEM_K4; p++) {
        int idx = tid + p * LTHREADS;
        w4s[idx] = Wg[idx];
    }
    ulonglong2 wreg[REG_K4];
#pragma unroll
    for (int s = 0; s < REG_K4; s++)
        wreg[s] = Wg[(SMEM_K4 + s) * GATES + n];

    h_s[tid]            = 0.0f;
    h_s[tid + LTHREADS] = 0.0f;
    __syncthreads();

    float cst[2] = {0.0f, 0.0f};

    for (int t = 0; t < SEQ; t++) {
        // Prefetch this step's xg (independent of h; DRAM latency hidden
        // under the 4K-cycle FMA block)
        float xg_v[2][4];
#pragma unroll
        for (int p = 0; p < 2; p++) {
            size_t base = ((size_t)((b0 + rp + p * 4) * SEQ + t)) * GATES + j;
#pragma unroll
            for (int g = 0; g < 4; g++)
                xg_v[p][g] = __ldg(&g_xg[base + g * HID]);
        }

        // -- FMA phase: gs[r][n] = sum_k h[r][k] * Whh[n][k] --
        unsigned long long acc[BR];
#pragma unroll
        for (int r = 0; r < BR; r++) acc[r] = 0ULL;

#pragma unroll 4
        for (int k4 = 0; k4 < SMEM_K4; k4++) {
            ulonglong2 w = w4s[k4 * GATES + n];
#pragma unroll
            for (int r = 0; r < BR; r++) {
                ulonglong2 hh = *(const ulonglong2*)&h_s[r * HID + k4 * 4];
                ffma2(acc[r], hh.x, w.x);
                ffma2(acc[r], hh.y, w.y);
            }
        }
#pragma unroll
        for (int s = 0; s < REG_K4; s++) {
            int k4 = SMEM_K4 + s;
#pragma unroll
            for (int r = 0; r < BR; r++) {
                ulonglong2 hh = *(const ulonglong2*)&h_s[r * HID + k4 * 4];
                ffma2(acc[r], hh.x, wreg[s].x);
                ffma2(acc[r], hh.y, wreg[s].y);
            }
        }

#pragma unroll
        for (int r = 0; r < BR; r++)
            gs[r * GATES + n] = hsum2(acc[r]);

        __syncthreads();

        // -- Elementwise phase: nonlinearity + state update --
#pragma unroll
        for (int p = 0; p < 2; p++) {
            int r = rp + p * 4;
            float gi = gs[r * GATES + j]             + xg_v[p][0];
            float gf = gs[r * GATES + 128 + j]       + xg_v[p][1];
            float gg = gs[r * GATES + 256 + j]       + xg_v[p][2];
            float go = gs[r * GATES + 384 + j]       + xg_v[p][3];
            float iv = sigmoid_f(gi);
            float fv = sigmoid_f(gf);
            float gv = tanh_f(gg);
            float ov = sigmoid_f(go);
            float cc = fv * cst[p] + iv * gv;
            cst[p] = cc;
            h_s[r * HID + j] = ov * tanh_f(cc);
        }
        __syncthreads();
    }

    // -- Output projection: out[b][o] = h[b] . W_out[o] + b_out[o] --
#pragma unroll
    for (int p = 0; p < 2; p++) {
        int idx = tid + p * LTHREADS;      // 0..1023 -> (r, o)
        int r = idx >> 7;
        int o = idx & 127;
        const float4* wo = (const float4*)(W_out + (size_t)o * HID);
        const float4* hrr = (const float4*)&h_s[r * HID];
        float s = __ldg(&b_out[o]);
#pragma unroll
        for (int k4 = 0; k4 < 32; k4++) {
            float4 w = wo[k4];
            float4 h = hrr[k4];
            s += w.x * h.x + w.y * h.y + w.z * h.z + w.w * h.w;
        }
        out[(size_t)(b0 + r) * NOUT + o] = s;
    }
}

// ---------------------------------------------------------------------------
// Launch (2 kernels)
// ---------------------------------------------------------------------------
extern "C" void kernel_launch(void* const* d_in, const int* in_sizes, int n_in,
                              void* d_out, int out_size) {
    const float* x     = (const float*)d_in[0];
    const float* W_ih  = (const float*)d_in[1];
    const float* W_hh  = (const float*)d_in[2];
    const float* b_ih  = (const float*)d_in[3];
    const float* b_hh  = (const float*)d_in[4];
    const float* W_out = (const float*)d_in[5];
    const float* b_out = (const float*)d_in[6];
    float* out = (float*)d_out;

    const int lstm_smem = SMEM_K4 * GATES * 16 + 4096 + BR * GATES * 4; // 192K+4K+16K = 212K
    cudaFuncSetAttribute(lstm_kernel,
                         cudaFuncAttributeMaxDynamicSharedMemorySize, lstm_smem);

    dim3 grid1((BATCH * SEQ) / 64, GATES / 64);
    xg_kernel<<<grid1, 256>>>(x, W_ih, W_hh, b_ih, b_hh);

    lstm_kernel<<<NCTA, LTHREADS, lstm_smem>>>(W_out, b_out, out);
}